// round 15
// baseline (speedup 1.0000x reference)
#include <cuda_runtime.h>
#include <cuda_bf16.h>
#include <math.h>

#define MAXN 50000
#define MAXE 800000

// ---------------- device scratch ----------------
__device__ __align__(16) float g_qt [(size_t)MAXN * 128];       // x@(WqWk^T) + gvec
__device__ __align__(16) __nv_bfloat16 g_xb[(size_t)MAXN * 64]; // x in bf16 (gather side)
__device__ __align__(16) __nv_bfloat16 g_v [(size_t)MAXN * 128];// projected v, bf16
__device__ __align__(16) float g_agg[(size_t)MAXN * 128];       // attention output
__device__ __align__(16) float g_M  [64 * 128];                 // Mcat = Wq Wk^T per head
__device__ __align__(16) float g_W2 [64 * 64];                  // Wskip @ Wc
__device__ float  g_gvec[128];                                   // Wk_h @ bq_h per head
__device__ float  g_b2[64];                                      // bskip@Wc + bc
__device__ int    g_esrc [MAXE];
__device__ int    g_edst [MAXE];
__device__ int    g_srcs [MAXE];
__device__ int    g_cnt  [MAXN];
__device__ int    g_cur  [MAXN];
__device__ int    g_rowptr[MAXN + 1];
__device__ int    g_blksum[64];
__device__ int    g_is64;
__device__ double g_stats[2];

// ---------------- packed fp32x2 helpers ----------------
__device__ __forceinline__ void fma2(unsigned long long& acc, unsigned long long a,
                                     unsigned long long b) {
    asm("fma.rn.f32x2 %0, %1, %2, %3;" : "=l"(acc) : "l"(a), "l"(b), "l"(acc));
}
__device__ __forceinline__ unsigned long long pack2(float x, float y) {
    unsigned long long r;
    asm("mov.b64 %0, {%1, %2};" : "=l"(r) : "f"(x), "f"(y));
    return r;
}
__device__ __forceinline__ float2 unpack2(unsigned long long v) {
    float2 r;
    asm("mov.b64 {%0, %1}, %2;" : "=f"(r.x), "=f"(r.y) : "l"(v));
    return r;
}

// ================= 1: fused setup = init | detect | precomputes =================
__global__ void k_setup(const void* __restrict__ ei, int n,
                        const float* __restrict__ Wq, const float* __restrict__ bq,
                        const float* __restrict__ Wk,
                        const float* __restrict__ Wsk, const float* __restrict__ bsk,
                        const float* __restrict__ Wc, const float* __restrict__ bc) {
    int nInit = (n + 255) >> 8;
    int b = blockIdx.x;
    if (b < nInit) {
        int i = b * 256 + threadIdx.x;
        if (i < n) { g_cnt[i] = 0; g_cur[i] = 0; }
        if (i == 0) { g_stats[0] = 0.0; g_stats[1] = 0.0; }
        return;
    }
    if (b == nInit) {
        if (threadIdx.x == 0) {
            const int* w = (const int*)ei;
            int all0 = 1;
            for (int i = 1; i < 64; i += 2) all0 &= (w[i] == 0);
            g_is64 = all0;
        }
        return;
    }
    int idx = (b - nInit - 1) * 256 + threadIdx.x;
    int g = idx >> 2, part = idx & 3;
    float s = 0.f;
    int valid = 0;
    float* dst = 0;
    if (g < 8192) {                      // Mcat
        int i = g >> 7, col = g & 127, h = col >> 6, j = col & 63;
        const float* wq = Wq + i * 128 + h * 64 + part * 16;
        const float* wk = Wk + j * 128 + h * 64 + part * 16;
#pragma unroll
        for (int c = 0; c < 16; c++) s = fmaf(wq[c], wk[c], s);
        dst = &g_M[g]; valid = 1;
    } else if (g < 12288) {              // W2
        int o = g - 8192, r = o >> 6, c = o & 63;
#pragma unroll
        for (int k = 0; k < 32; k++)
            s = fmaf(Wsk[r * 128 + part * 32 + k], Wc[(part * 32 + k) * 64 + c], s);
        dst = &g_W2[o]; valid = 1;
    } else if (g < 12352) {              // b2
        int c = g - 12288;
        if (part == 0) s = bc[c];
#pragma unroll
        for (int k = 0; k < 32; k++)
            s = fmaf(bsk[part * 32 + k], Wc[(part * 32 + k) * 64 + c], s);
        dst = &g_b2[c]; valid = 1;
    } else if (g < 12480) {              // gvec
        int o = g - 12352, h = o >> 6, i = o & 63;
#pragma unroll
        for (int j = 0; j < 16; j++)
            s = fmaf(Wk[i * 128 + h * 64 + part * 16 + j], bq[h * 64 + part * 16 + j], s);
        dst = &g_gvec[o]; valid = 1;
    }
    s += __shfl_xor_sync(0xffffffffu, s, 1);
    s += __shfl_xor_sync(0xffffffffu, s, 2);
    if (valid && part == 0) *dst = s;
}

// ================= 2: convert + fused dst histogram =================
__global__ void k_convert(const void* __restrict__ ei, int e) {
    int i = blockIdx.x * blockDim.x + threadIdx.x;
    if (i >= 2 * e) return;
    int v;
    if (g_is64) v = (int)((const long long*)ei)[i];
    else        v = ((const int*)ei)[i];
    if (i < e) g_esrc[i] = v;
    else { g_edst[i - e] = v; atomicAdd(&g_cnt[v], 1); }
}

// ================= 3: x -> bf16 copy =================
__global__ void k_xb(const float* __restrict__ x, int n) {
    int i = blockIdx.x * 256 + threadIdx.x;
    if (i < n * 16) {
        float4 xv = ((const float4*)x)[i];
        __nv_bfloat162 lo = __floats2bfloat162_rn(xv.x, xv.y);
        __nv_bfloat162 hi = __floats2bfloat162_rn(xv.z, xv.w);
        uint2 u;
        u.x = *(unsigned*)&lo;
        u.y = *(unsigned*)&hi;
        ((uint2*)g_xb)[i] = u;
    }
}

// ================= 4: qt | v GEMM, f32x2, TM=16/TN=2 (PROFILED SLOT) =================
// grid: (ceil(n/128), 4); blockIdx.y: bit1 = m (0=qt,1=v), bit0 = column half.
__global__ void __launch_bounds__(256) k_gemm2(
        const float* __restrict__ x,
        const float* __restrict__ Wv, const float* __restrict__ bv,
        int n) {
    __shared__ float Xs[32][132];   // [k][row], 128 rows
    __shared__ float Ws[32][64];    // [k][col], 64-col half
    int m    = blockIdx.y >> 1;
    int half = blockIdx.y & 1;
    const float* W    = (m == 0) ? (const float*)g_M : Wv;
    const float* bias = (m == 0) ? (const float*)g_gvec : bv;

    int tx = threadIdx.x & 31;      // 2 cols: half*64 + tx*2
    int ty = threadIdx.x >> 5;      // 16 rows: ty*16..+15 (warp-uniform -> broadcast A)
    int row0 = blockIdx.x * 128;

    unsigned long long acc2[8][2];  // [row-pair p][col j]: rows (2p,2p+1)
#pragma unroll
    for (int p = 0; p < 8; p++) { acc2[p][0] = 0ull; acc2[p][1] = 0ull; }

    for (int kc = 0; kc < 2; kc++) {
        // X tile: 128 rows x 32 k, k-major
#pragma unroll
        for (int it = 0; it < 4; it++) {
            int idx = threadIdx.x + it * 256;          // 0..1023
            int r = idx >> 3, kq = idx & 7;
            float4 xv = make_float4(0.f, 0.f, 0.f, 0.f);
            if (row0 + r < n) xv = ((const float4*)x)[(size_t)(row0 + r) * 16 + kc * 8 + kq];
            Xs[kq * 4 + 0][r] = xv.x;
            Xs[kq * 4 + 1][r] = xv.y;
            Xs[kq * 4 + 2][r] = xv.z;
            Xs[kq * 4 + 3][r] = xv.w;
        }
        // W tile: 32 k x 64 cols (this half)
#pragma unroll
        for (int it = 0; it < 2; it++) {
            int idx = threadIdx.x + it * 256;          // 0..511
            int k = idx >> 4, c4 = idx & 15;
            *(float4*)&Ws[k][c4 * 4] =
                ((const float4*)W)[(size_t)(kc * 32 + k) * 32 + half * 16 + c4];
        }
        __syncthreads();
#pragma unroll
        for (int k = 0; k < 32; k++) {
            float4 a0 = *(const float4*)&Xs[k][ty * 16];
            float4 a1 = *(const float4*)&Xs[k][ty * 16 + 4];
            float4 a2 = *(const float4*)&Xs[k][ty * 16 + 8];
            float4 a3 = *(const float4*)&Xs[k][ty * 16 + 12];
            float2 b  = *(const float2*)&Ws[k][tx * 2];
            unsigned long long B0 = pack2(b.x, b.x);
            unsigned long long B1 = pack2(b.y, b.y);
            unsigned long long A[8] = {pack2(a0.x, a0.y), pack2(a0.z, a0.w),
                                       pack2(a1.x, a1.y), pack2(a1.z, a1.w),
                                       pack2(a2.x, a2.y), pack2(a2.z, a2.w),
                                       pack2(a3.x, a3.y), pack2(a3.z, a3.w)};
#pragma unroll
            for (int p = 0; p < 8; p++) {
                fma2(acc2[p][0], A[p], B0);
                fma2(acc2[p][1], A[p], B1);
            }
        }
        __syncthreads();
    }
    float2 bv2 = *(const float2*)&bias[half * 64 + tx * 2];
#pragma unroll
    for (int p = 0; p < 8; p++) {
        float2 c0 = unpack2(acc2[p][0]);   // col tx*2,   rows (2p,2p+1)
        float2 c1 = unpack2(acc2[p][1]);   // col tx*2+1, rows (2p,2p+1)
        float ov[2][2] = {{c0.x + bv2.x, c1.x + bv2.y}, {c0.y + bv2.x, c1.y + bv2.y}};
#pragma unroll
        for (int h = 0; h < 2; h++) {
            int r = row0 + ty * 16 + p * 2 + h;
            if (r < n) {
                if (m == 0) {
                    *(float2*)&g_qt[(size_t)r * 128 + half * 64 + tx * 2] =
                        make_float2(ov[h][0], ov[h][1]);
                } else {
                    __nv_bfloat162 bb = __floats2bfloat162_rn(ov[h][0], ov[h][1]);
                    *(unsigned*)&g_v[(size_t)r * 128 + half * 64 + tx * 2] = *(unsigned*)&bb;
                }
            }
        }
    }
}

// ================= 5: scan stage 1 =================
__global__ void k_scan1(int n) {
    __shared__ int sh[1024];
    int tid = threadIdx.x;
    int i = blockIdx.x * 1024 + tid;
    int v = (i < n) ? g_cnt[i] : 0;
    sh[tid] = v;
    __syncthreads();
    for (int off = 1; off < 1024; off <<= 1) {
        int t = (tid >= off) ? sh[tid - off] : 0;
        __syncthreads();
        sh[tid] += t;
        __syncthreads();
    }
    if (i < n) g_rowptr[i] = sh[tid] - v;
    if (tid == 1023) g_blksum[blockIdx.x] = sh[1023];
}

// ================= 6: scan stages 2+3 fused =================
__global__ void __launch_bounds__(1024) k_scan23(int n, int nb) {
    __shared__ int pref;
    int bid = blockIdx.x;
    if (threadIdx.x == 0) {
        int acc = 0;
        for (int b = 0; b < bid; b++) acc += g_blksum[b];
        pref = acc;
        if (bid == nb - 1) g_rowptr[n] = acc + g_blksum[nb - 1];
    }
    __syncthreads();
    int i = bid * 1024 + threadIdx.x;
    if (i < n) g_rowptr[i] += pref;
}

// ================= 7: CSR scatter =================
__global__ void k_scatter(int e) {
    int i = blockIdx.x * blockDim.x + threadIdx.x;
    if (i < e) {
        int dst = g_edst[i];
        int pos = g_rowptr[dst] + atomicAdd(&g_cur[dst], 1);
        g_srcs[pos] = g_esrc[i];
    }
}

// ================= 8: attention =================
__device__ __forceinline__ float2 bf2f(unsigned u) {
    return __bfloat1622float2(*(__nv_bfloat162*)&u);
}

__global__ void __launch_bounds__(256) k_attn(int n) {
    int node = blockIdx.x * 8 + (threadIdx.x >> 5);
    if (node >= n) return;
    int lane = threadIdx.x & 31;
    int l15 = lane & 15;

    float4 qt = *(const float4*)&g_qt[(size_t)node * 128 + lane * 4];
    int beg = g_rowptr[node], end = g_rowptr[node + 1];

    const uint2* xb = (const uint2*)g_xb;
    const uint2* vb = (const uint2*)g_v;

    float denom = 0.f;
    float4 acc = make_float4(0.f, 0.f, 0.f, 0.f);

    int t = beg;
    for (; t + 4 <= end; t += 4) {
        int s0 = g_srcs[t + 0], s1 = g_srcs[t + 1], s2 = g_srcs[t + 2], s3 = g_srcs[t + 3];
        uint2 X0 = xb[(size_t)s0 * 16 + l15];
        uint2 X1 = xb[(size_t)s1 * 16 + l15];
        uint2 X2 = xb[(size_t)s2 * 16 + l15];
        uint2 X3 = xb[(size_t)s3 * 16 + l15];
        uint2 V0 = vb[(size_t)s0 * 32 + lane];
        uint2 V1 = vb[(size_t)s1 * 32 + lane];
        uint2 V2 = vb[(size_t)s2 * 32 + lane];
        uint2 V3 = vb[(size_t)s3 * 32 + lane];

        float2 a, b;
        a = bf2f(X0.x); b = bf2f(X0.y);
        float d0 = qt.x * a.x + qt.y * a.y + qt.z * b.x + qt.w * b.y;
        a = bf2f(X1.x); b = bf2f(X1.y);
        float d1 = qt.x * a.x + qt.y * a.y + qt.z * b.x + qt.w * b.y;
        a = bf2f(X2.x); b = bf2f(X2.y);
        float d2 = qt.x * a.x + qt.y * a.y + qt.z * b.x + qt.w * b.y;
        a = bf2f(X3.x); b = bf2f(X3.y);
        float d3 = qt.x * a.x + qt.y * a.y + qt.z * b.x + qt.w * b.y;
#pragma unroll
        for (int off = 8; off > 0; off >>= 1) {
            d0 += __shfl_xor_sync(0xffffffffu, d0, off);
            d1 += __shfl_xor_sync(0xffffffffu, d1, off);
            d2 += __shfl_xor_sync(0xffffffffu, d2, off);
            d3 += __shfl_xor_sync(0xffffffffu, d3, off);
        }
        float w0 = __expf(d0 * 0.125f);
        float w1 = __expf(d1 * 0.125f);
        float w2 = __expf(d2 * 0.125f);
        float w3 = __expf(d3 * 0.125f);
        denom += (w0 + w1) + (w2 + w3);

        a = bf2f(V0.x); b = bf2f(V0.y);
        acc.x = fmaf(w0, a.x, acc.x); acc.y = fmaf(w0, a.y, acc.y);
        acc.z = fmaf(w0, b.x, acc.z); acc.w = fmaf(w0, b.y, acc.w);
        a = bf2f(V1.x); b = bf2f(V1.y);
        acc.x = fmaf(w1, a.x, acc.x); acc.y = fmaf(w1, a.y, acc.y);
        acc.z = fmaf(w1, b.x, acc.z); acc.w = fmaf(w1, b.y, acc.w);
        a = bf2f(V2.x); b = bf2f(V2.y);
        acc.x = fmaf(w2, a.x, acc.x); acc.y = fmaf(w2, a.y, acc.y);
        acc.z = fmaf(w2, b.x, acc.z); acc.w = fmaf(w2, b.y, acc.w);
        a = bf2f(V3.x); b = bf2f(V3.y);
        acc.x = fmaf(w3, a.x, acc.x); acc.y = fmaf(w3, a.y, acc.y);
        acc.z = fmaf(w3, b.x, acc.z); acc.w = fmaf(w3, b.y, acc.w);
    }
    for (; t < end; t++) {
        int s = g_srcs[t];
        uint2 X = xb[(size_t)s * 16 + l15];
        uint2 V = vb[(size_t)s * 32 + lane];
        float2 a = bf2f(X.x);
        float2 b = bf2f(X.y);
        float d = qt.x * a.x + qt.y * a.y + qt.z * b.x + qt.w * b.y;
#pragma unroll
        for (int off = 8; off > 0; off >>= 1) d += __shfl_xor_sync(0xffffffffu, d, off);
        float w = __expf(d * 0.125f);
        denom += w;
        a = bf2f(V.x); b = bf2f(V.y);
        acc.x = fmaf(w, a.x, acc.x); acc.y = fmaf(w, a.y, acc.y);
        acc.z = fmaf(w, b.x, acc.z); acc.w = fmaf(w, b.y, acc.w);
    }
    float inv = 1.f / (denom + 1e-16f);
    acc.x *= inv; acc.y *= inv; acc.z *= inv; acc.w *= inv;
    ((float4*)g_agg)[(size_t)node * 32 + lane] = acc;
}

// ================= 9: out = agg@Wc + x@W2 + b2, f32x2, TM=16/TN=2, fused LN stats =================
__global__ void __launch_bounds__(256) k_final(const float* __restrict__ x,
                                               const float* __restrict__ Wc,
                                               float* __restrict__ out, int n) {
    __shared__ float Xs[32][132];
    __shared__ float Ws[32][64];
    __shared__ float rs[8], rss[8];

    int tx = threadIdx.x & 31;     // 2 cols: tx*2
    int ty = threadIdx.x >> 5;     // 16 rows
    int row0 = blockIdx.x * 128;

    unsigned long long acc2[8][2];
#pragma unroll
    for (int p = 0; p < 8; p++) { acc2[p][0] = 0ull; acc2[p][1] = 0ull; }

    for (int kc = 0; kc < 6; kc++) {
#pragma unroll
        for (int it = 0; it < 4; it++) {
            int idx = threadIdx.x + it * 256;
            int r = idx >> 3, kq = idx & 7;
            float4 av = make_float4(0.f, 0.f, 0.f, 0.f);
            if (row0 + r < n) {
                if (kc < 4) av = ((const float4*)g_agg)[(size_t)(row0 + r) * 32 + kc * 8 + kq];
                else        av = ((const float4*)x)[(size_t)(row0 + r) * 16 + (kc - 4) * 8 + kq];
            }
            Xs[kq * 4 + 0][r] = av.x;
            Xs[kq * 4 + 1][r] = av.y;
            Xs[kq * 4 + 2][r] = av.z;
            Xs[kq * 4 + 3][r] = av.w;
        }
#pragma unroll
        for (int it = 0; it < 2; it++) {
            int idx = threadIdx.x + it * 256;
            int k = idx >> 4, c4 = idx & 15;
            float4 wv;
            if (kc < 4) wv = ((const float4*)Wc)[(kc * 32 + k) * 16 + c4];
            else        wv = ((const float4*)g_W2)[((kc - 4) * 32 + k) * 16 + c4];
            *(float4*)&Ws[k][c4 * 4] = wv;
        }
        __syncthreads();
#pragma unroll
        for (int k = 0; k < 32; k++) {
            float4 a0 = *(const float4*)&Xs[k][ty * 16];
            float4 a1 = *(const float4*)&Xs[k][ty * 16 + 4];
            float4 a2 = *(const float4*)&Xs[k][ty * 16 + 8];
            float4 a3 = *(const float4*)&Xs[k][ty * 16 + 12];
            float2 b  = *(const float2*)&Ws[k][tx * 2];
            unsigned long long B0 = pack2(b.x, b.x);
            unsigned long long B1 = pack2(b.y, b.y);
            unsigned long long A[8] = {pack2(a0.x, a0.y), pack2(a0.z, a0.w),
                                       pack2(a1.x, a1.y), pack2(a1.z, a1.w),
                                       pack2(a2.x, a2.y), pack2(a2.z, a2.w),
                                       pack2(a3.x, a3.y), pack2(a3.z, a3.w)};
#pragma unroll
            for (int p = 0; p < 8; p++) {
                fma2(acc2[p][0], A[p], B0);
                fma2(acc2[p][1], A[p], B1);
            }
        }
        __syncthreads();
    }

    float2 b2 = *(const float2*)&g_b2[tx * 2];
    float s = 0.f, ss = 0.f;
#pragma unroll
    for (int p = 0; p < 8; p++) {
        float2 c0 = unpack2(acc2[p][0]);
        float2 c1 = unpack2(acc2[p][1]);
        float ov[2][2] = {{c0.x + b2.x, c1.x + b2.y}, {c0.y + b2.x, c1.y + b2.y}};
#pragma unroll
        for (int h = 0; h < 2; h++) {
            int r = row0 + ty * 16 + p * 2 + h;
            if (r < n) {
                *(float2*)&out[(size_t)r * 64 + tx * 2] = make_float2(ov[h][0], ov[h][1]);
                s += ov[h][0] + ov[h][1];
                ss += ov[h][0] * ov[h][0] + ov[h][1] * ov[h][1];
            }
        }
    }
#pragma unroll
    for (int off = 16; off > 0; off >>= 1) {
        s  += __shfl_xor_sync(0xffffffffu, s, off);
        ss += __shfl_xor_sync(0xffffffffu, ss, off);
    }
    int wid = threadIdx.x >> 5, lane = threadIdx.x & 31;
    if (lane == 0) { rs[wid] = s; rss[wid] = ss; }
    __syncthreads();
    if (threadIdx.x == 0) {
        double S = 0.0, SS = 0.0;
        for (int w = 0; w < 8; w++) { S += (double)rs[w]; SS += (double)rss[w]; }
        atomicAdd(&g_stats[0], S);
        atomicAdd(&g_stats[1], SS);
    }
}

// ================= 10: graph-level LayerNorm =================
__global__ void k_norm(float* __restrict__ out, const float* __restrict__ gamma,
                       const float* __restrict__ beta, int total) {
    int i = blockIdx.x * blockDim.x + threadIdx.x;
    if (i < total) {
        double M = (double)total;
        double mean = g_stats[0] / M;
        double var  = g_stats[1] / M - mean * mean;
        if (var < 0.0) var = 0.0;
        float stdv = (float)sqrt(var);
        float v = out[i];
        int d = i & 63;
        out[i] = (v - (float)mean) / (stdv + 1e-5f) * __ldg(&gamma[d]) + __ldg(&beta[d]);
    }
}

// ---------------- launch ----------------
extern "C" void kernel_launch(void* const* d_in, const int* in_sizes, int n_in,
                              void* d_out, int out_size) {
    const float* x    = (const float*)d_in[0];
    const void*  ei   = d_in[1];
    const float* Wq   = (const float*)d_in[2];
    const float* bq   = (const float*)d_in[3];
    const float* Wk   = (const float*)d_in[4];
    const float* Wv   = (const float*)d_in[6];
    const float* bv   = (const float*)d_in[7];
    const float* Wsk  = (const float*)d_in[8];
    const float* bsk  = (const float*)d_in[9];
    const float* Wc   = (const float*)d_in[10];
    const float* bc   = (const float*)d_in[11];
    const float* gam  = (const float*)d_in[12];
    const float* bet  = (const float*)d_in[13];
    float* out = (float*)d_out;

    int n = in_sizes[0] / 64;
    int e = in_sizes[1] / 2;

    int nInit = (n + 255) / 256;
    k_setup<<<nInit + 1 + 195, 256>>>(ei, n, Wq, bq, Wk, Wsk, bsk, Wc, bc);  // #1
    k_convert<<<(2 * e + 255) / 256, 256>>>(ei, e);                           // #2
    k_xb<<<(n * 16 + 255) / 256, 256>>>(x, n);                                // #3
    k_gemm2<<<dim3((n + 127) / 128, 4), 256>>>(x, Wv, bv, n);                 // #4 <- capture
    int nb = (n + 1023) / 1024;
    k_scan1<<<nb, 1024>>>(n);                                                 // #5
    k_scan23<<<nb, 1024>>>(n, nb);                                            // #6
    k_scatter<<<(e + 255) / 256, 256>>>(e);                                   // #7
    k_attn<<<(n + 7) / 8, 256>>>(n);                                          // #8
    k_final<<<(n + 127) / 128, 256>>>(x, Wc, out, n);                         // #9
    k_norm<<<(n * 64 + 255) / 256, 256>>>(out, gam, bet, n * 64);             // #10
}

// round 16
// speedup vs baseline: 1.0076x; 1.0076x over previous
#include <cuda_runtime.h>
#include <cuda_bf16.h>
#include <math.h>

#define MAXN 50000
#define MAXE 800000

// ---------------- device scratch ----------------
__device__ __align__(16) float g_qt [(size_t)MAXN * 128];       // x@(WqWk^T) + gvec
__device__ __align__(16) __nv_bfloat16 g_xb[(size_t)MAXN * 64]; // x in bf16 (gather side)
__device__ __align__(16) __nv_bfloat16 g_v [(size_t)MAXN * 128];// projected v, bf16
__device__ __align__(16) float g_agg[(size_t)MAXN * 128];       // attention output
__device__ __align__(16) float g_M  [64 * 128];                 // Mcat = Wq Wk^T per head
__device__ __align__(16) float g_W2 [64 * 64];                  // Wskip @ Wc
__device__ float  g_gvec[128];                                   // Wk_h @ bq_h per head
__device__ float  g_b2[64];                                      // bskip@Wc + bc
__device__ int    g_esrc [MAXE];
__device__ int    g_edst [MAXE];
__device__ int    g_srcs [MAXE];
__device__ int    g_cnt  [MAXN];
__device__ int    g_cur  [MAXN];
__device__ int    g_rowptr[MAXN + 1];
__device__ int    g_blksum[64];
__device__ int    g_is64;
__device__ double g_stats[2];

// ---------------- host-side stream/event resources (created once, pre-main) ----------------
static cudaStream_t s_edge;
static cudaEvent_t  s_evFork, s_evJoin;
namespace {
struct ResInit {
    ResInit() {
        cudaStreamCreateWithFlags(&s_edge, cudaStreamNonBlocking);
        cudaEventCreateWithFlags(&s_evFork, cudaEventDisableTiming);
        cudaEventCreateWithFlags(&s_evJoin, cudaEventDisableTiming);
    }
};
static ResInit g_resInit;
}

// ---------------- packed fp32x2 helpers ----------------
__device__ __forceinline__ void fma2(unsigned long long& acc, unsigned long long a,
                                     unsigned long long b) {
    asm("fma.rn.f32x2 %0, %1, %2, %3;" : "=l"(acc) : "l"(a), "l"(b), "l"(acc));
}
__device__ __forceinline__ unsigned long long pack2(float x, float y) {
    unsigned long long r;
    asm("mov.b64 %0, {%1, %2};" : "=l"(r) : "f"(x), "f"(y));
    return r;
}
__device__ __forceinline__ float2 unpack2(unsigned long long v) {
    float2 r;
    asm("mov.b64 {%0, %1}, %2;" : "=f"(r.x), "=f"(r.y) : "l"(v));
    return r;
}

// ================= fused setup = init | detect | precomputes =================
__global__ void k_setup(const void* __restrict__ ei, int n,
                        const float* __restrict__ Wq, const float* __restrict__ bq,
                        const float* __restrict__ Wk,
                        const float* __restrict__ Wsk, const float* __restrict__ bsk,
                        const float* __restrict__ Wc, const float* __restrict__ bc) {
    int nInit = (n + 255) >> 8;
    int b = blockIdx.x;
    if (b < nInit) {
        int i = b * 256 + threadIdx.x;
        if (i < n) { g_cnt[i] = 0; g_cur[i] = 0; }
        if (i == 0) { g_stats[0] = 0.0; g_stats[1] = 0.0; }
        return;
    }
    if (b == nInit) {
        if (threadIdx.x == 0) {
            const int* w = (const int*)ei;
            int all0 = 1;
            for (int i = 1; i < 64; i += 2) all0 &= (w[i] == 0);
            g_is64 = all0;
        }
        return;
    }
    int idx = (b - nInit - 1) * 256 + threadIdx.x;
    int g = idx >> 2, part = idx & 3;
    float s = 0.f;
    int valid = 0;
    float* dst = 0;
    if (g < 8192) {                      // Mcat
        int i = g >> 7, col = g & 127, h = col >> 6, j = col & 63;
        const float* wq = Wq + i * 128 + h * 64 + part * 16;
        const float* wk = Wk + j * 128 + h * 64 + part * 16;
#pragma unroll
        for (int c = 0; c < 16; c++) s = fmaf(wq[c], wk[c], s);
        dst = &g_M[g]; valid = 1;
    } else if (g < 12288) {              // W2
        int o = g - 8192, r = o >> 6, c = o & 63;
#pragma unroll
        for (int k = 0; k < 32; k++)
            s = fmaf(Wsk[r * 128 + part * 32 + k], Wc[(part * 32 + k) * 64 + c], s);
        dst = &g_W2[o]; valid = 1;
    } else if (g < 12352) {              // b2
        int c = g - 12288;
        if (part == 0) s = bc[c];
#pragma unroll
        for (int k = 0; k < 32; k++)
            s = fmaf(bsk[part * 32 + k], Wc[(part * 32 + k) * 64 + c], s);
        dst = &g_b2[c]; valid = 1;
    } else if (g < 12480) {              // gvec
        int o = g - 12352, h = o >> 6, i = o & 63;
#pragma unroll
        for (int j = 0; j < 16; j++)
            s = fmaf(Wk[i * 128 + h * 64 + part * 16 + j], bq[h * 64 + part * 16 + j], s);
        dst = &g_gvec[o]; valid = 1;
    }
    s += __shfl_xor_sync(0xffffffffu, s, 1);
    s += __shfl_xor_sync(0xffffffffu, s, 2);
    if (valid && part == 0) *dst = s;
}

// ================= edge chain: convert + hist =================
__global__ void k_convert(const void* __restrict__ ei, int e) {
    int i = blockIdx.x * blockDim.x + threadIdx.x;
    if (i >= 2 * e) return;
    int v;
    if (g_is64) v = (int)((const long long*)ei)[i];
    else        v = ((const int*)ei)[i];
    if (i < e) g_esrc[i] = v;
    else { g_edst[i - e] = v; atomicAdd(&g_cnt[v], 1); }
}

// ================= edge chain: scan stage 1 =================
__global__ void k_scan1(int n) {
    __shared__ int sh[1024];
    int tid = threadIdx.x;
    int i = blockIdx.x * 1024 + tid;
    int v = (i < n) ? g_cnt[i] : 0;
    sh[tid] = v;
    __syncthreads();
    for (int off = 1; off < 1024; off <<= 1) {
        int t = (tid >= off) ? sh[tid - off] : 0;
        __syncthreads();
        sh[tid] += t;
        __syncthreads();
    }
    if (i < n) g_rowptr[i] = sh[tid] - v;
    if (tid == 1023) g_blksum[blockIdx.x] = sh[1023];
}

// ================= edge chain: scan stages 2+3 fused =================
__global__ void __launch_bounds__(1024) k_scan23(int n, int nb) {
    __shared__ int pref;
    int bid = blockIdx.x;
    if (threadIdx.x == 0) {
        int acc = 0;
        for (int b = 0; b < bid; b++) acc += g_blksum[b];
        pref = acc;
        if (bid == nb - 1) g_rowptr[n] = acc + g_blksum[nb - 1];
    }
    __syncthreads();
    int i = bid * 1024 + threadIdx.x;
    if (i < n) g_rowptr[i] += pref;
}

// ================= edge chain: CSR scatter =================
__global__ void k_scatter(int e) {
    int i = blockIdx.x * blockDim.x + threadIdx.x;
    if (i < e) {
        int dst = g_edst[i];
        int pos = g_rowptr[dst] + atomicAdd(&g_cur[dst], 1);
        g_srcs[pos] = g_esrc[i];
    }
}

// ================= projection chain: x -> bf16 copy =================
__global__ void k_xb(const float* __restrict__ x, int n) {
    int i = blockIdx.x * 256 + threadIdx.x;
    if (i < n * 16) {
        float4 xv = ((const float4*)x)[i];
        __nv_bfloat162 lo = __floats2bfloat162_rn(xv.x, xv.y);
        __nv_bfloat162 hi = __floats2bfloat162_rn(xv.z, xv.w);
        uint2 u;
        u.x = *(unsigned*)&lo;
        u.y = *(unsigned*)&hi;
        ((uint2*)g_xb)[i] = u;
    }
}

// ================= projection chain: qt | v GEMM (R14 tile: TM=8/TN=4, f32x2) =================
__global__ void __launch_bounds__(256) k_gemm2(
        const float* __restrict__ x,
        const float* __restrict__ Wv, const float* __restrict__ bv,
        int n) {
    __shared__ float Xs[32][68];
    __shared__ float Ws[32][128];
    int m = blockIdx.y;
    const float* W    = (m == 0) ? (const float*)g_M : Wv;
    const float* bias = (m == 0) ? (const float*)g_gvec : bv;

    int tx = threadIdx.x & 31;
    int ty = threadIdx.x >> 5;
    int row0 = blockIdx.x * 64;

    unsigned long long acc2[4][4];
#pragma unroll
    for (int p = 0; p < 4; p++)
#pragma unroll
        for (int j = 0; j < 4; j++) acc2[p][j] = 0ull;

    for (int kc = 0; kc < 2; kc++) {
#pragma unroll
        for (int it = 0; it < 2; it++) {
            int idx = threadIdx.x + it * 256;
            int r = idx >> 3, kq = idx & 7;
            float4 xv = make_float4(0.f, 0.f, 0.f, 0.f);
            if (row0 + r < n) xv = ((const float4*)x)[(size_t)(row0 + r) * 16 + kc * 8 + kq];
            Xs[kq * 4 + 0][r] = xv.x;
            Xs[kq * 4 + 1][r] = xv.y;
            Xs[kq * 4 + 2][r] = xv.z;
            Xs[kq * 4 + 3][r] = xv.w;
        }
#pragma unroll
        for (int it = 0; it < 4; it++) {
            int idx = threadIdx.x + it * 256;
            ((float4*)Ws)[idx] = ((const float4*)W)[kc * 1024 + idx];
        }
        __syncthreads();
#pragma unroll
        for (int k = 0; k < 32; k++) {
            float4 a0 = *(const float4*)&Xs[k][ty * 8];
            float4 a1 = *(const float4*)&Xs[k][ty * 8 + 4];
            float4 b  = *(const float4*)&Ws[k][tx * 4];
            unsigned long long A[4] = {pack2(a0.x, a0.y), pack2(a0.z, a0.w),
                                       pack2(a1.x, a1.y), pack2(a1.z, a1.w)};
            unsigned long long B[4] = {pack2(b.x, b.x), pack2(b.y, b.y),
                                       pack2(b.z, b.z), pack2(b.w, b.w)};
#pragma unroll
            for (int p = 0; p < 4; p++) {
                fma2(acc2[p][0], A[p], B[0]);
                fma2(acc2[p][1], A[p], B[1]);
                fma2(acc2[p][2], A[p], B[2]);
                fma2(acc2[p][3], A[p], B[3]);
            }
        }
        __syncthreads();
    }
    float4 bv4 = *(const float4*)&bias[tx * 4];
#pragma unroll
    for (int p = 0; p < 4; p++) {
        float2 c0 = unpack2(acc2[p][0]);
        float2 c1 = unpack2(acc2[p][1]);
        float2 c2 = unpack2(acc2[p][2]);
        float2 c3 = unpack2(acc2[p][3]);
        float rowv[2][4] = {{c0.x, c1.x, c2.x, c3.x}, {c0.y, c1.y, c2.y, c3.y}};
#pragma unroll
        for (int h = 0; h < 2; h++) {
            int r = row0 + ty * 8 + p * 2 + h;
            if (r < n) {
                float o0 = rowv[h][0] + bv4.x, o1 = rowv[h][1] + bv4.y;
                float o2 = rowv[h][2] + bv4.z, o3 = rowv[h][3] + bv4.w;
                if (m == 0) {
                    *(float4*)&g_qt[(size_t)r * 128 + tx * 4] = make_float4(o0, o1, o2, o3);
                } else {
                    __nv_bfloat162 lo = __floats2bfloat162_rn(o0, o1);
                    __nv_bfloat162 hi = __floats2bfloat162_rn(o2, o3);
                    uint2 u;
                    u.x = *(unsigned*)&lo;
                    u.y = *(unsigned*)&hi;
                    *(uint2*)&g_v[(size_t)r * 128 + tx * 4] = u;
                }
            }
        }
    }
}

// ================= attention =================
__device__ __forceinline__ float2 bf2f(unsigned u) {
    return __bfloat1622float2(*(__nv_bfloat162*)&u);
}

__global__ void __launch_bounds__(256) k_attn(int n) {
    int node = blockIdx.x * 8 + (threadIdx.x >> 5);
    if (node >= n) return;
    int lane = threadIdx.x & 31;
    int l15 = lane & 15;

    float4 qt = *(const float4*)&g_qt[(size_t)node * 128 + lane * 4];
    int beg = g_rowptr[node], end = g_rowptr[node + 1];

    const uint2* xb = (const uint2*)g_xb;
    const uint2* vb = (const uint2*)g_v;

    float denom = 0.f;
    float4 acc = make_float4(0.f, 0.f, 0.f, 0.f);

    int t = beg;
    for (; t + 4 <= end; t += 4) {
        int s0 = g_srcs[t + 0], s1 = g_srcs[t + 1], s2 = g_srcs[t + 2], s3 = g_srcs[t + 3];
        uint2 X0 = xb[(size_t)s0 * 16 + l15];
        uint2 X1 = xb[(size_t)s1 * 16 + l15];
        uint2 X2 = xb[(size_t)s2 * 16 + l15];
        uint2 X3 = xb[(size_t)s3 * 16 + l15];
        uint2 V0 = vb[(size_t)s0 * 32 + lane];
        uint2 V1 = vb[(size_t)s1 * 32 + lane];
        uint2 V2 = vb[(size_t)s2 * 32 + lane];
        uint2 V3 = vb[(size_t)s3 * 32 + lane];

        float2 a, b;
        a = bf2f(X0.x); b = bf2f(X0.y);
        float d0 = qt.x * a.x + qt.y * a.y + qt.z * b.x + qt.w * b.y;
        a = bf2f(X1.x); b = bf2f(X1.y);
        float d1 = qt.x * a.x + qt.y * a.y + qt.z * b.x + qt.w * b.y;
        a = bf2f(X2.x); b = bf2f(X2.y);
        float d2 = qt.x * a.x + qt.y * a.y + qt.z * b.x + qt.w * b.y;
        a = bf2f(X3.x); b = bf2f(X3.y);
        float d3 = qt.x * a.x + qt.y * a.y + qt.z * b.x + qt.w * b.y;
#pragma unroll
        for (int off = 8; off > 0; off >>= 1) {
            d0 += __shfl_xor_sync(0xffffffffu, d0, off);
            d1 += __shfl_xor_sync(0xffffffffu, d1, off);
            d2 += __shfl_xor_sync(0xffffffffu, d2, off);
            d3 += __shfl_xor_sync(0xffffffffu, d3, off);
        }
        float w0 = __expf(d0 * 0.125f);
        float w1 = __expf(d1 * 0.125f);
        float w2 = __expf(d2 * 0.125f);
        float w3 = __expf(d3 * 0.125f);
        denom += (w0 + w1) + (w2 + w3);

        a = bf2f(V0.x); b = bf2f(V0.y);
        acc.x = fmaf(w0, a.x, acc.x); acc.y = fmaf(w0, a.y, acc.y);
        acc.z = fmaf(w0, b.x, acc.z); acc.w = fmaf(w0, b.y, acc.w);
        a = bf2f(V1.x); b = bf2f(V1.y);
        acc.x = fmaf(w1, a.x, acc.x); acc.y = fmaf(w1, a.y, acc.y);
        acc.z = fmaf(w1, b.x, acc.z); acc.w = fmaf(w1, b.y, acc.w);
        a = bf2f(V2.x); b = bf2f(V2.y);
        acc.x = fmaf(w2, a.x, acc.x); acc.y = fmaf(w2, a.y, acc.y);
        acc.z = fmaf(w2, b.x, acc.z); acc.w = fmaf(w2, b.y, acc.w);
        a = bf2f(V3.x); b = bf2f(V3.y);
        acc.x = fmaf(w3, a.x, acc.x); acc.y = fmaf(w3, a.y, acc.y);
        acc.z = fmaf(w3, b.x, acc.z); acc.w = fmaf(w3, b.y, acc.w);
    }
    for (; t < end; t++) {
        int s = g_srcs[t];
        uint2 X = xb[(size_t)s * 16 + l15];
        uint2 V = vb[(size_t)s * 32 + lane];
        float2 a = bf2f(X.x);
        float2 b = bf2f(X.y);
        float d = qt.x * a.x + qt.y * a.y + qt.z * b.x + qt.w * b.y;
#pragma unroll
        for (int off = 8; off > 0; off >>= 1) d += __shfl_xor_sync(0xffffffffu, d, off);
        float w = __expf(d * 0.125f);
        denom += w;
        a = bf2f(V.x); b = bf2f(V.y);
        acc.x = fmaf(w, a.x, acc.x); acc.y = fmaf(w, a.y, acc.y);
        acc.z = fmaf(w, b.x, acc.z); acc.w = fmaf(w, b.y, acc.w);
    }
    float inv = 1.f / (denom + 1e-16f);
    acc.x *= inv; acc.y *= inv; acc.z *= inv; acc.w *= inv;
    ((float4*)g_agg)[(size_t)node * 32 + lane] = acc;
}

// ================= final GEMM (R14 tile) + fused LN stats =================
__global__ void __launch_bounds__(256) k_final(const float* __restrict__ x,
                                               const float* __restrict__ Wc,
                                               float* __restrict__ out, int n) {
    __shared__ float Xs[32][132];
    __shared__ float Ws[32][64];
    __shared__ float rs[8], rss[8];

    int tx = threadIdx.x & 15;
    int ty = threadIdx.x >> 4;
    int row0 = blockIdx.x * 128;

    unsigned long long acc2[4][4];
#pragma unroll
    for (int p = 0; p < 4; p++)
#pragma unroll
        for (int j = 0; j < 4; j++) acc2[p][j] = 0ull;

    for (int kc = 0; kc < 6; kc++) {
#pragma unroll
        for (int it = 0; it < 4; it++) {
            int idx = threadIdx.x + it * 256;
            int r = idx >> 3, kq = idx & 7;
            float4 av = make_float4(0.f, 0.f, 0.f, 0.f);
            if (row0 + r < n) {
                if (kc < 4) av = ((const float4*)g_agg)[(size_t)(row0 + r) * 32 + kc * 8 + kq];
                else        av = ((const float4*)x)[(size_t)(row0 + r) * 16 + (kc - 4) * 8 + kq];
            }
            Xs[kq * 4 + 0][r] = av.x;
            Xs[kq * 4 + 1][r] = av.y;
            Xs[kq * 4 + 2][r] = av.z;
            Xs[kq * 4 + 3][r] = av.w;
        }
#pragma unroll
        for (int it = 0; it < 2; it++) {
            int idx = threadIdx.x + it * 256;
            int k = idx >> 4, c4 = idx & 15;
            float4 wv;
            if (kc < 4) wv = ((const float4*)Wc)[(kc * 32 + k) * 16 + c4];
            else        wv = ((const float4*)g_W2)[((kc - 4) * 32 + k) * 16 + c4];
            *(float4*)&Ws[k][c4 * 4] = wv;
        }
        __syncthreads();
#pragma unroll
        for (int k = 0; k < 32; k++) {
            float4 a0 = *(const float4*)&Xs[k][ty * 8];
            float4 a1 = *(const float4*)&Xs[k][ty * 8 + 4];
            float4 b  = *(const float4*)&Ws[k][tx * 4];
            unsigned long long A[4] = {pack2(a0.x, a0.y), pack2(a0.z, a0.w),
                                       pack2(a1.x, a1.y), pack2(a1.z, a1.w)};
            unsigned long long B[4] = {pack2(b.x, b.x), pack2(b.y, b.y),
                                       pack2(b.z, b.z), pack2(b.w, b.w)};
#pragma unroll
            for (int p = 0; p < 4; p++) {
                fma2(acc2[p][0], A[p], B[0]);
                fma2(acc2[p][1], A[p], B[1]);
                fma2(acc2[p][2], A[p], B[2]);
                fma2(acc2[p][3], A[p], B[3]);
            }
        }
        __syncthreads();
    }

    float4 b2 = *(const float4*)&g_b2[tx * 4];
    float s = 0.f, ss = 0.f;
#pragma unroll
    for (int p = 0; p < 4; p++) {
        float2 c0 = unpack2(acc2[p][0]);
        float2 c1 = unpack2(acc2[p][1]);
        float2 c2 = unpack2(acc2[p][2]);
        float2 c3 = unpack2(acc2[p][3]);
        float rowv[2][4] = {{c0.x, c1.x, c2.x, c3.x}, {c0.y, c1.y, c2.y, c3.y}};
#pragma unroll
        for (int h = 0; h < 2; h++) {
            int r = row0 + ty * 8 + p * 2 + h;
            if (r < n) {
                float4 o = make_float4(rowv[h][0] + b2.x, rowv[h][1] + b2.y,
                                       rowv[h][2] + b2.z, rowv[h][3] + b2.w);
                *(float4*)&out[(size_t)r * 64 + tx * 4] = o;
                s += (o.x + o.y) + (o.z + o.w);
                ss += o.x * o.x + o.y * o.y + o.z * o.z + o.w * o.w;
            }
        }
    }
#pragma unroll
    for (int off = 16; off > 0; off >>= 1) {
        s  += __shfl_xor_sync(0xffffffffu, s, off);
        ss += __shfl_xor_sync(0xffffffffu, ss, off);
    }
    int wid = threadIdx.x >> 5, lane = threadIdx.x & 31;
    if (lane == 0) { rs[wid] = s; rss[wid] = ss; }
    __syncthreads();
    if (threadIdx.x == 0) {
        double S = 0.0, SS = 0.0;
        for (int w = 0; w < 8; w++) { S += (double)rs[w]; SS += (double)rss[w]; }
        atomicAdd(&g_stats[0], S);
        atomicAdd(&g_stats[1], SS);
    }
}

// ================= graph-level LayerNorm =================
__global__ void k_norm(float* __restrict__ out, const float* __restrict__ gamma,
                       const float* __restrict__ beta, int total) {
    int i = blockIdx.x * blockDim.x + threadIdx.x;
    if (i < total) {
        double M = (double)total;
        double mean = g_stats[0] / M;
        double var  = g_stats[1] / M - mean * mean;
        if (var < 0.0) var = 0.0;
        float stdv = (float)sqrt(var);
        float v = out[i];
        int d = i & 63;
        out[i] = (v - (float)mean) / (stdv + 1e-5f) * __ldg(&gamma[d]) + __ldg(&beta[d]);
    }
}

// ---------------- launch: fork edge chain onto second stream ----------------
extern "C" void kernel_launch(void* const* d_in, const int* in_sizes, int n_in,
                              void* d_out, int out_size) {
    const float* x    = (const float*)d_in[0];
    const void*  ei   = d_in[1];
    const float* Wq   = (const float*)d_in[2];
    const float* bq   = (const float*)d_in[3];
    const float* Wk   = (const float*)d_in[4];
    const float* Wv   = (const float*)d_in[6];
    const float* bv   = (const float*)d_in[7];
    const float* Wsk  = (const float*)d_in[8];
    const float* bsk  = (const float*)d_in[9];
    const float* Wc   = (const float*)d_in[10];
    const float* bc   = (const float*)d_in[11];
    const float* gam  = (const float*)d_in[12];
    const float* bet  = (const float*)d_in[13];
    float* out = (float*)d_out;

    int n = in_sizes[0] / 64;
    int e = in_sizes[1] / 2;
    int nInit = (n + 255) / 256;
    int nb = (n + 1023) / 1024;

    // main stream: setup (init + detect + precomputes)
    k_setup<<<nInit + 1 + 195, 256>>>(ei, n, Wq, bq, Wk, Wsk, bsk, Wc, bc);

    // fork: edge chain on s_edge (depends on init + detect from setup)
    cudaEventRecord(s_evFork, 0);
    cudaStreamWaitEvent(s_edge, s_evFork, 0);
    k_convert<<<(2 * e + 255) / 256, 256, 0, s_edge>>>(ei, e);
    k_scan1<<<nb, 1024, 0, s_edge>>>(n);
    k_scan23<<<nb, 1024, 0, s_edge>>>(n, nb);
    k_scatter<<<(e + 255) / 256, 256, 0, s_edge>>>(e);
    cudaEventRecord(s_evJoin, s_edge);

    // main stream: projection chain (independent of edge chain)
    k_xb<<<(n * 16 + 255) / 256, 256>>>(x, n);
    k_gemm2<<<dim3((n + 63) / 64, 2), 256>>>(x, Wv, bv, n);

    // join: attention needs both chains
    cudaStreamWaitEvent(0, s_evJoin, 0);
    k_attn<<<(n + 7) / 8, 256>>>(n);
    k_final<<<(n + 127) / 128, 256>>>(x, Wc, out, n);
    k_norm<<<(n * 64 + 255) / 256, 256>>>(out, gam, bet, n * 64);
}

// round 17
// speedup vs baseline: 1.0373x; 1.0295x over previous
#include <cuda_runtime.h>
#include <cuda_bf16.h>
#include <math.h>

#define MAXN 50000
#define MAXE 800000

// ---------------- device scratch ----------------
__device__ __align__(16) float g_qt [(size_t)MAXN * 128];       // x@(WqWk^T) + gvec
__device__ __align__(16) __nv_bfloat16 g_xb[(size_t)MAXN * 64]; // x in bf16 (gather side)
__device__ __align__(16) __nv_bfloat16 g_v [(size_t)MAXN * 128];// projected v, bf16
__device__ __align__(16) float g_agg[(size_t)MAXN * 128];       // attention output
__device__ __align__(16) __nv_bfloat16 g_MbT [128 * 64];        // (WqWk^T)^T, bf16 [n][k]
__device__ __align__(16) __nv_bfloat16 g_WvbT[128 * 64];        // Wv^T, bf16 [n][k]
__device__ __align__(16) float g_W2 [64 * 64];                  // Wskip @ Wc
__device__ float  g_gvec[128];                                   // Wk_h @ bq_h per head
__device__ float  g_b2[64];                                      // bskip@Wc + bc
__device__ int    g_esrc [MAXE];
__device__ int    g_edst [MAXE];
__device__ int    g_srcs [MAXE];
__device__ int    g_cnt  [MAXN];
__device__ int    g_cur  [MAXN];
__device__ int    g_rowptr[MAXN + 1];
__device__ int    g_blksum[64];
__device__ int    g_is64;
__device__ double g_stats[2];

// ---------------- packed fp32x2 helpers (k_final) ----------------
__device__ __forceinline__ void fma2(unsigned long long& acc, unsigned long long a,
                                     unsigned long long b) {
    asm("fma.rn.f32x2 %0, %1, %2, %3;" : "=l"(acc) : "l"(a), "l"(b), "l"(acc));
}
__device__ __forceinline__ unsigned long long pack2(float x, float y) {
    unsigned long long r;
    asm("mov.b64 %0, {%1, %2};" : "=l"(r) : "f"(x), "f"(y));
    return r;
}
__device__ __forceinline__ float2 unpack2(unsigned long long v) {
    float2 r;
    asm("mov.b64 {%0, %1}, %2;" : "=f"(r.x), "=f"(r.y) : "l"(v));
    return r;
}

// ================= 1: fused setup = init | detect | precomputes =================
// precompute outputs (4 threads each): [0,8192) Mcat->g_MbT, [8192,12288) W2,
// [12288,12352) b2, [12352,12480) gvec, [12480,20672) Wv->g_WvbT
__global__ void k_setup(const void* __restrict__ ei, int n,
                        const float* __restrict__ Wq, const float* __restrict__ bq,
                        const float* __restrict__ Wk, const float* __restrict__ Wv,
                        const float* __restrict__ Wsk, const float* __restrict__ bsk,
                        const float* __restrict__ Wc, const float* __restrict__ bc) {
    int nInit = (n + 255) >> 8;
    int b = blockIdx.x;
    if (b < nInit) {
        int i = b * 256 + threadIdx.x;
        if (i < n) { g_cnt[i] = 0; g_cur[i] = 0; }
        if (i == 0) { g_stats[0] = 0.0; g_stats[1] = 0.0; }
        return;
    }
    if (b == nInit) {
        if (threadIdx.x == 0) {
            const int* w = (const int*)ei;
            int all0 = 1;
            for (int i = 1; i < 64; i += 2) all0 &= (w[i] == 0);
            g_is64 = all0;
        }
        return;
    }
    int idx = (b - nInit - 1) * 256 + threadIdx.x;
    int g = idx >> 2, part = idx & 3;
    float s = 0.f;
    if (g < 8192) {                      // Mcat[i][col] -> g_MbT[col][i] (bf16)
        int i = g >> 7, col = g & 127, h = col >> 6, j = col & 63;
        const float* wq = Wq + i * 128 + h * 64 + part * 16;
        const float* wk = Wk + j * 128 + h * 64 + part * 16;
#pragma unroll
        for (int c = 0; c < 16; c++) s = fmaf(wq[c], wk[c], s);
        s += __shfl_xor_sync(0xffffffffu, s, 1);
        s += __shfl_xor_sync(0xffffffffu, s, 2);
        if (part == 0) g_MbT[col * 64 + i] = __float2bfloat16(s);
    } else if (g < 12288) {              // W2
        int o = g - 8192, r = o >> 6, c = o & 63;
#pragma unroll
        for (int k = 0; k < 32; k++)
            s = fmaf(Wsk[r * 128 + part * 32 + k], Wc[(part * 32 + k) * 64 + c], s);
        s += __shfl_xor_sync(0xffffffffu, s, 1);
        s += __shfl_xor_sync(0xffffffffu, s, 2);
        if (part == 0) g_W2[o] = s;
    } else if (g < 12352) {              // b2
        int c = g - 12288;
        if (part == 0) s = bc[c];
#pragma unroll
        for (int k = 0; k < 32; k++)
            s = fmaf(bsk[part * 32 + k], Wc[(part * 32 + k) * 64 + c], s);
        s += __shfl_xor_sync(0xffffffffu, s, 1);
        s += __shfl_xor_sync(0xffffffffu, s, 2);
        if (part == 0) g_b2[c] = s;
    } else if (g < 12480) {              // gvec
        int o = g - 12352, h = o >> 6, i = o & 63;
#pragma unroll
        for (int j = 0; j < 16; j++)
            s = fmaf(Wk[i * 128 + h * 64 + part * 16 + j], bq[h * 64 + part * 16 + j], s);
        s += __shfl_xor_sync(0xffffffffu, s, 1);
        s += __shfl_xor_sync(0xffffffffu, s, 2);
        if (part == 0) g_gvec[o] = s;
    } else if (g < 20672) {              // Wv[k][ncol] -> g_WvbT[ncol][k] (bf16)
        if (part == 0) {
            int g2 = g - 12480;
            int k = g2 >> 7, ncol = g2 & 127;
            g_WvbT[ncol * 64 + k] = __float2bfloat16(Wv[k * 128 + ncol]);
        }
    }
}

// ================= 2: convert + fused dst histogram =================
__global__ void k_convert(const void* __restrict__ ei, int e) {
    int i = blockIdx.x * blockDim.x + threadIdx.x;
    if (i >= 2 * e) return;
    int v;
    if (g_is64) v = (int)((const long long*)ei)[i];
    else        v = ((const int*)ei)[i];
    if (i < e) g_esrc[i] = v;
    else { g_edst[i - e] = v; atomicAdd(&g_cnt[v], 1); }
}

// ================= 3: scan stage 1 =================
__global__ void k_scan1(int n) {
    __shared__ int sh[1024];
    int tid = threadIdx.x;
    int i = blockIdx.x * 1024 + tid;
    int v = (i < n) ? g_cnt[i] : 0;
    sh[tid] = v;
    __syncthreads();
    for (int off = 1; off < 1024; off <<= 1) {
        int t = (tid >= off) ? sh[tid - off] : 0;
        __syncthreads();
        sh[tid] += t;
        __syncthreads();
    }
    if (i < n) g_rowptr[i] = sh[tid] - v;
    if (tid == 1023) g_blksum[blockIdx.x] = sh[1023];
}

// ================= 4: qt | v GEMM via bf16 mma.sync (PROFILED SLOT) =================
// BM=64, BN=128 (full), block 256 = 8 warps: wm = w&3 (16-row tile), wn = w>>2 (64-col half).
// A: x tile in smem bf16 (row-major); m==1 blocks also emit g_xb from the same conversion.
// B: bf16 [n][k] pre-transposed weights, fragments via __ldg (16 KB, L1-resident).
__global__ void __launch_bounds__(256) k_gemm2(
        const float* __restrict__ x, const float* __restrict__ bv, int n) {
    __shared__ __nv_bfloat16 As[64][72];
    int m = blockIdx.y;
    const __nv_bfloat16* WbT = (m == 0) ? g_MbT : g_WvbT;
    int row0 = blockIdx.x * 64;
    int tid = threadIdx.x;

    // ---- load + convert x tile (and write g_xb from the m==1 pass) ----
#pragma unroll
    for (int it = 0; it < 4; it++) {
        int idx = tid + it * 256;             // 0..1023
        int r = idx >> 4, q = idx & 15;
        float4 xv = make_float4(0.f, 0.f, 0.f, 0.f);
        int ok = (row0 + r < n);
        if (ok) xv = ((const float4*)x)[(size_t)(row0 + r) * 16 + q];
        __nv_bfloat162 lo = __floats2bfloat162_rn(xv.x, xv.y);
        __nv_bfloat162 hi = __floats2bfloat162_rn(xv.z, xv.w);
        uint2 u;
        u.x = *(unsigned*)&lo;
        u.y = *(unsigned*)&hi;
        *(uint2*)&As[r][q * 4] = u;
        if (m == 1 && ok) ((uint2*)g_xb)[(size_t)(row0 + r) * 16 + q] = u;
    }
    __syncthreads();

    int lane = tid & 31, w = tid >> 5;
    int wm = w & 3, wn = w >> 2;
    int lr = lane >> 2;              // 0..7
    int lc = (lane & 3) * 2;         // 0,2,4,6

    float acc[8][4];
#pragma unroll
    for (int nt = 0; nt < 8; nt++)
#pragma unroll
        for (int j = 0; j < 4; j++) acc[nt][j] = 0.f;

#pragma unroll
    for (int ks = 0; ks < 4; ks++) {
        int k0 = ks * 16;
        unsigned a0 = *(const unsigned*)&As[wm * 16 + lr][k0 + lc];
        unsigned a1 = *(const unsigned*)&As[wm * 16 + lr + 8][k0 + lc];
        unsigned a2 = *(const unsigned*)&As[wm * 16 + lr][k0 + lc + 8];
        unsigned a3 = *(const unsigned*)&As[wm * 16 + lr + 8][k0 + lc + 8];
#pragma unroll
        for (int nt = 0; nt < 8; nt++) {
            int nrow = wn * 64 + nt * 8 + lr;
            unsigned b0 = __ldg((const unsigned*)&WbT[nrow * 64 + k0 + lc]);
            unsigned b1 = __ldg((const unsigned*)&WbT[nrow * 64 + k0 + lc + 8]);
            asm volatile(
                "mma.sync.aligned.m16n8k16.row.col.f32.bf16.bf16.f32 "
                "{%0,%1,%2,%3}, {%4,%5,%6,%7}, {%8,%9}, {%0,%1,%2,%3};"
                : "+f"(acc[nt][0]), "+f"(acc[nt][1]), "+f"(acc[nt][2]), "+f"(acc[nt][3])
                : "r"(a0), "r"(a1), "r"(a2), "r"(a3), "r"(b0), "r"(b1));
        }
    }

    // ---- epilogue ----
    const float* bias = (m == 0) ? (const float*)g_gvec : bv;
    int rA = row0 + wm * 16 + lr;
    int rB = rA + 8;
#pragma unroll
    for (int nt = 0; nt < 8; nt++) {
        int col = wn * 64 + nt * 8 + lc;
        float2 bb = *(const float2*)&bias[col];
        float o0 = acc[nt][0] + bb.x, o1 = acc[nt][1] + bb.y;   // row rA
        float o2 = acc[nt][2] + bb.x, o3 = acc[nt][3] + bb.y;   // row rB
        if (m == 0) {
            if (rA < n) *(float2*)&g_qt[(size_t)rA * 128 + col] = make_float2(o0, o1);
            if (rB < n) *(float2*)&g_qt[(size_t)rB * 128 + col] = make_float2(o2, o3);
        } else {
            if (rA < n) {
                __nv_bfloat162 p = __floats2bfloat162_rn(o0, o1);
                *(unsigned*)&g_v[(size_t)rA * 128 + col] = *(unsigned*)&p;
            }
            if (rB < n) {
                __nv_bfloat162 p = __floats2bfloat162_rn(o2, o3);
                *(unsigned*)&g_v[(size_t)rB * 128 + col] = *(unsigned*)&p;
            }
        }
    }
}

// ================= 5: scan stages 2+3 fused =================
__global__ void __launch_bounds__(1024) k_scan23(int n, int nb) {
    __shared__ int pref;
    int bid = blockIdx.x;
    if (threadIdx.x == 0) {
        int acc = 0;
        for (int b = 0; b < bid; b++) acc += g_blksum[b];
        pref = acc;
        if (bid == nb - 1) g_rowptr[n] = acc + g_blksum[nb - 1];
    }
    __syncthreads();
    int i = bid * 1024 + threadIdx.x;
    if (i < n) g_rowptr[i] += pref;
}

// ================= 6: CSR scatter =================
__global__ void k_scatter(int e) {
    int i = blockIdx.x * blockDim.x + threadIdx.x;
    if (i < e) {
        int dst = g_edst[i];
        int pos = g_rowptr[dst] + atomicAdd(&g_cur[dst], 1);
        g_srcs[pos] = g_esrc[i];
    }
}

// ================= 7: attention =================
__device__ __forceinline__ float2 bf2f(unsigned u) {
    return __bfloat1622float2(*(__nv_bfloat162*)&u);
}

__global__ void __launch_bounds__(256) k_attn(int n) {
    int node = blockIdx.x * 8 + (threadIdx.x >> 5);
    if (node >= n) return;
    int lane = threadIdx.x & 31;
    int l15 = lane & 15;

    float4 qt = *(const float4*)&g_qt[(size_t)node * 128 + lane * 4];
    int beg = g_rowptr[node], end = g_rowptr[node + 1];

    const uint2* xb = (const uint2*)g_xb;
    const uint2* vb = (const uint2*)g_v;

    float denom = 0.f;
    float4 acc = make_float4(0.f, 0.f, 0.f, 0.f);

    int t = beg;
    for (; t + 4 <= end; t += 4) {
        int s0 = g_srcs[t + 0], s1 = g_srcs[t + 1], s2 = g_srcs[t + 2], s3 = g_srcs[t + 3];
        uint2 X0 = xb[(size_t)s0 * 16 + l15];
        uint2 X1 = xb[(size_t)s1 * 16 + l15];
        uint2 X2 = xb[(size_t)s2 * 16 + l15];
        uint2 X3 = xb[(size_t)s3 * 16 + l15];
        uint2 V0 = vb[(size_t)s0 * 32 + lane];
        uint2 V1 = vb[(size_t)s1 * 32 + lane];
        uint2 V2 = vb[(size_t)s2 * 32 + lane];
        uint2 V3 = vb[(size_t)s3 * 32 + lane];

        float2 a, b;
        a = bf2f(X0.x); b = bf2f(X0.y);
        float d0 = qt.x * a.x + qt.y * a.y + qt.z * b.x + qt.w * b.y;
        a = bf2f(X1.x); b = bf2f(X1.y);
        float d1 = qt.x * a.x + qt.y * a.y + qt.z * b.x + qt.w * b.y;
        a = bf2f(X2.x); b = bf2f(X2.y);
        float d2 = qt.x * a.x + qt.y * a.y + qt.z * b.x + qt.w * b.y;
        a = bf2f(X3.x); b = bf2f(X3.y);
        float d3 = qt.x * a.x + qt.y * a.y + qt.z * b.x + qt.w * b.y;
#pragma unroll
        for (int off = 8; off > 0; off >>= 1) {
            d0 += __shfl_xor_sync(0xffffffffu, d0, off);
            d1 += __shfl_xor_sync(0xffffffffu, d1, off);
            d2 += __shfl_xor_sync(0xffffffffu, d2, off);
            d3 += __shfl_xor_sync(0xffffffffu, d3, off);
        }
        float w0 = __expf(d0 * 0.125f);
        float w1 = __expf(d1 * 0.125f);
        float w2 = __expf(d2 * 0.125f);
        float w3 = __expf(d3 * 0.125f);
        denom += (w0 + w1) + (w2 + w3);

        a = bf2f(V0.x); b = bf2f(V0.y);
        acc.x = fmaf(w0, a.x, acc.x); acc.y = fmaf(w0, a.y, acc.y);
        acc.z = fmaf(w0, b.x, acc.z); acc.w = fmaf(w0, b.y, acc.w);
        a = bf2f(V1.x); b = bf2f(V1.y);
        acc.x = fmaf(w1, a.x, acc.x); acc.y = fmaf(w1, a.y, acc.y);
        acc.z = fmaf(w1, b.x, acc.z); acc.w = fmaf(w1, b.y, acc.w);
        a = bf2f(V2.x); b = bf2f(V2.y);
        acc.x = fmaf(w2, a.x, acc.x); acc.y = fmaf(w2, a.y, acc.y);
        acc.z = fmaf(w2, b.x, acc.z); acc.w = fmaf(w2, b.y, acc.w);
        a = bf2f(V3.x); b = bf2f(V3.y);
        acc.x = fmaf(w3, a.x, acc.x); acc.y = fmaf(w3, a.y, acc.y);
        acc.z = fmaf(w3, b.x, acc.z); acc.w = fmaf(w3, b.y, acc.w);
    }
    for (; t < end; t++) {
        int s = g_srcs[t];
        uint2 X = xb[(size_t)s * 16 + l15];
        uint2 V = vb[(size_t)s * 32 + lane];
        float2 a = bf2f(X.x);
        float2 b = bf2f(X.y);
        float d = qt.x * a.x + qt.y * a.y + qt.z * b.x + qt.w * b.y;
#pragma unroll
        for (int off = 8; off > 0; off >>= 1) d += __shfl_xor_sync(0xffffffffu, d, off);
        float w = __expf(d * 0.125f);
        denom += w;
        a = bf2f(V.x); b = bf2f(V.y);
        acc.x = fmaf(w, a.x, acc.x); acc.y = fmaf(w, a.y, acc.y);
        acc.z = fmaf(w, b.x, acc.z); acc.w = fmaf(w, b.y, acc.w);
    }
    float inv = 1.f / (denom + 1e-16f);
    acc.x *= inv; acc.y *= inv; acc.z *= inv; acc.w *= inv;
    ((float4*)g_agg)[(size_t)node * 32 + lane] = acc;
}

// ================= 8: final GEMM (f32x2) + fused LN stats =================
__global__ void __launch_bounds__(256) k_final(const float* __restrict__ x,
                                               const float* __restrict__ Wc,
                                               float* __restrict__ out, int n) {
    __shared__ float Xs[32][132];
    __shared__ float Ws[32][64];
    __shared__ float rs[8], rss[8];

    int tx = threadIdx.x & 15;
    int ty = threadIdx.x >> 4;
    int row0 = blockIdx.x * 128;

    unsigned long long acc2[4][4];
#pragma unroll
    for (int p = 0; p < 4; p++)
#pragma unroll
        for (int j = 0; j < 4; j++) acc2[p][j] = 0ull;

    for (int kc = 0; kc < 6; kc++) {
#pragma unroll
        for (int it = 0; it < 4; it++) {
            int idx = threadIdx.x + it * 256;
            int r = idx >> 3, kq = idx & 7;
            float4 av = make_float4(0.f, 0.f, 0.f, 0.f);
            if (row0 + r < n) {
                if (kc < 4) av = ((const float4*)g_agg)[(size_t)(row0 + r) * 32 + kc * 8 + kq];
                else        av = ((const float4*)x)[(size_t)(row0 + r) * 16 + (kc - 4) * 8 + kq];
            }
            Xs[kq * 4 + 0][r] = av.x;
            Xs[kq * 4 + 1][r] = av.y;
            Xs[kq * 4 + 2][r] = av.z;
            Xs[kq * 4 + 3][r] = av.w;
        }
#pragma unroll
        for (int it = 0; it < 2; it++) {
            int idx = threadIdx.x + it * 256;
            int k = idx >> 4, c4 = idx & 15;
            float4 wv;
            if (kc < 4) wv = ((const float4*)Wc)[(kc * 32 + k) * 16 + c4];
            else        wv = ((const float4*)g_W2)[((kc - 4) * 32 + k) * 16 + c4];
            *(float4*)&Ws[k][c4 * 4] = wv;
        }
        __syncthreads();
#pragma unroll
        for (int k = 0; k < 32; k++) {
            float4 a0 = *(const float4*)&Xs[k][ty * 8];
            float4 a1 = *(const float4*)&Xs[k][ty * 8 + 4];
            float4 b  = *(const float4*)&Ws[k][tx * 4];
            unsigned long long A[4] = {pack2(a0.x, a0.y), pack2(a0.z, a0.w),
                                       pack2(a1.x, a1.y), pack2(a1.z, a1.w)};
            unsigned long long B[4] = {pack2(b.x, b.x), pack2(b.y, b.y),
                                       pack2(b.z, b.z), pack2(b.w, b.w)};
#pragma unroll
            for (int p = 0; p < 4; p++) {
                fma2(acc2[p][0], A[p], B[0]);
                fma2(acc2[p][1], A[p], B[1]);
                fma2(acc2[p][2], A[p], B[2]);
                fma2(acc2[p][3], A[p], B[3]);
            }
        }
        __syncthreads();
    }

    float4 b2 = *(const float4*)&g_b2[tx * 4];
    float s = 0.f, ss = 0.f;
#pragma unroll
    for (int p = 0; p < 4; p++) {
        float2 c0 = unpack2(acc2[p][0]);
        float2 c1 = unpack2(acc2[p][1]);
        float2 c2 = unpack2(acc2[p][2]);
        float2 c3 = unpack2(acc2[p][3]);
        float rowv[2][4] = {{c0.x, c1.x, c2.x, c3.x}, {c0.y, c1.y, c2.y, c3.y}};
#pragma unroll
        for (int h = 0; h < 2; h++) {
            int r = row0 + ty * 8 + p * 2 + h;
            if (r < n) {
                float4 o = make_float4(rowv[h][0] + b2.x, rowv[h][1] + b2.y,
                                       rowv[h][2] + b2.z, rowv[h][3] + b2.w);
                *(float4*)&out[(size_t)r * 64 + tx * 4] = o;
                s += (o.x + o.y) + (o.z + o.w);
                ss += o.x * o.x + o.y * o.y + o.z * o.z + o.w * o.w;
            }
        }
    }
#pragma unroll
    for (int off = 16; off > 0; off >>= 1) {
        s  += __shfl_xor_sync(0xffffffffu, s, off);
        ss += __shfl_xor_sync(0xffffffffu, ss, off);
    }
    int wid = threadIdx.x >> 5, lane = threadIdx.x & 31;
    if (lane == 0) { rs[wid] = s; rss[wid] = ss; }
    __syncthreads();
    if (threadIdx.x == 0) {
        double S = 0.0, SS = 0.0;
        for (int w = 0; w < 8; w++) { S += (double)rs[w]; SS += (double)rss[w]; }
        atomicAdd(&g_stats[0], S);
        atomicAdd(&g_stats[1], SS);
    }
}

// ================= 9: graph-level LayerNorm =================
__global__ void k_norm(float* __restrict__ out, const float* __restrict__ gamma,
                       const float* __restrict__ beta, int total) {
    int i = blockIdx.x * blockDim.x + threadIdx.x;
    if (i < total) {
        double M = (double)total;
        double mean = g_stats[0] / M;
        double var  = g_stats[1] / M - mean * mean;
        if (var < 0.0) var = 0.0;
        float stdv = (float)sqrt(var);
        float v = out[i];
        int d = i & 63;
        out[i] = (v - (float)mean) / (stdv + 1e-5f) * __ldg(&gamma[d]) + __ldg(&beta[d]);
    }
}

// ---------------- launch (sequential; gemm2 at profiled slot #4) ----------------
extern "C" void kernel_launch(void* const* d_in, const int* in_sizes, int n_in,
                              void* d_out, int out_size) {
    const float* x    = (const float*)d_in[0];
    const void*  ei   = d_in[1];
    const float* Wq   = (const float*)d_in[2];
    const float* bq   = (const float*)d_in[3];
    const float* Wk   = (const float*)d_in[4];
    const float* Wv   = (const float*)d_in[6];
    const float* bv   = (const float*)d_in[7];
    const float* Wsk  = (const float*)d_in[8];
    const float* bsk  = (const float*)d_in[9];
    const float* Wc   = (const float*)d_in[10];
    const float* bc   = (const float*)d_in[11];
    const float* gam  = (const float*)d_in[12];
    const float* bet  = (const float*)d_in[13];
    float* out = (float*)d_out;

    int n = in_sizes[0] / 64;
    int e = in_sizes[1] / 2;
    int nInit = (n + 255) / 256;
    int nb = (n + 1023) / 1024;
    int nPrep = (20672 * 4 + 255) / 256;   // 323

    k_setup<<<nInit + 1 + nPrep, 256>>>(ei, n, Wq, bq, Wk, Wv, Wsk, bsk, Wc, bc); // #1
    k_convert<<<(2 * e + 255) / 256, 256>>>(ei, e);                               // #2
    k_scan1<<<nb, 1024>>>(n);                                                     // #3
    k_gemm2<<<dim3((n + 63) / 64, 2), 256>>>(x, bv, n);                           // #4 <- capture
    k_scan23<<<nb, 1024>>>(n, nb);                                                // #5
    k_scatter<<<(e + 255) / 256, 256>>>(e);                                       // #6
    k_attn<<<(n + 7) / 8, 256>>>(n);                                              // #7
    k_final<<<(n + 127) / 128, 256>>>(x, Wc, out, n);                             // #8
    k_norm<<<(n * 64 + 255) / 256, 256>>>(out, gam, bet, n * 64);                 // #9
}